// round 10
// baseline (speedup 1.0000x reference)
#include <cuda_runtime.h>
#include <math.h>
#include <stdint.h>

#define ATT_SCALE 0.08838834764831845f   // 128^-0.5
#define PW 36                            // u32-word pitch of bf16 tiles (4 mod 32 -> conflict-free)

#define TILE_W  (128*PW)                 // 4608 words per 128-row tile
#define TILEQ_W (192*PW)                 // 6912 words per 192-row tile
#define SMEM_SZ 73728                    // pk: 4 x 128-row tiles
#define SMEM_ATT 75776                   // attn: 4 tiles + 2KB reduction buffer
#define SMEM_Q  101376                   // qproj: tiles (92160) / 192x132 fp32 stage

// ----------------- scratch (device globals; only referenced from device code) -----------------
__device__ __align__(128) float g_q  [4*128*16384];   // (B,C,H,W)
__device__ __align__(128) float g_k  [4*128*16384];   // (B,C,H,W)
__device__ __align__(128) float g_vT [4*128*16384];   // (B,C,W,H)
__device__ __align__(128) float g_xs [65536*128];     // (B,H,W,C)
__device__ __align__(128) float g_z  [4*64*16384];    // 50 offset-tap projections per batch
__device__ __align__(128) float g_coords[65536*2];
__device__ __align__(128) float g_Weff[50*128];       // [jt][c] fold of Wc2@Wc1
__device__ __align__(128) float g_zbias[50];          // Weff @ bq
__device__ __align__(128) float g_beff[2];            // Wc2 @ bc1
__device__ __align__(128) float g_Wqz[192*128];       // rows 0-127 Wq, 128-177 Weff@Wq, 178-191 zero
// preconverted weight tiles
__device__ __align__(128) unsigned g_WthQ[2][TILEQ_W];
__device__ __align__(128) unsigned g_WtlQ[2][TILEQ_W];
__device__ __align__(128) unsigned g_Wth[3][2][TILE_W];   // 0=Wk, 1=Wv, 2=Wo
__device__ __align__(128) unsigned g_Wtl[3][2][TILE_W];

// ----------------- helpers -----------------
static __device__ __forceinline__ void mmabf(float c[4], const unsigned a[4],
                                             unsigned b0, unsigned b1) {
    asm volatile("mma.sync.aligned.m16n8k16.row.col.f32.bf16.bf16.f32 "
        "{%0,%1,%2,%3},{%4,%5,%6,%7},{%8,%9},{%0,%1,%2,%3};"
        : "+f"(c[0]), "+f"(c[1]), "+f"(c[2]), "+f"(c[3])
        : "r"(a[0]), "r"(a[1]), "r"(a[2]), "r"(a[3]), "r"(b0), "r"(b1));
}
static __device__ __forceinline__ void ldsm4(unsigned r[4], unsigned addr) {
    asm volatile("ldmatrix.sync.aligned.m8n8.x4.shared.b16 {%0,%1,%2,%3},[%4];"
        : "=r"(r[0]), "=r"(r[1]), "=r"(r[2]), "=r"(r[3]) : "r"(addr));
}
static __device__ __forceinline__ unsigned packh(float x0, float x1) {
    unsigned h; asm("cvt.rn.bf16x2.f32 %0,%1,%2;" : "=r"(h) : "f"(x1), "f"(x0)); return h;
}
static __device__ __forceinline__ unsigned packl(float x0, float x1, unsigned h) {
    float h0 = __uint_as_float(h << 16), h1 = __uint_as_float(h & 0xffff0000u);
    return packh(x0 - h0, x1 - h1);
}

// load a ROWSx64 fp32 chunk (cols kc*64..) into hi/lo bf16-pair word tiles; NTHR threads
template<int ROWS, int NTHR>
static __device__ __forceinline__ void fill_chunkR(const float* __restrict__ src, int ld, int kc,
                                                   float scale, unsigned* th, unsigned* tl, int tid) {
#pragma unroll
    for (int it = 0; it < ROWS*16/NTHR; it++) {
        int idx = it*NTHR + tid;
        int r = idx >> 4, c4 = (idx & 15)*4;
        float4 v = *(const float4*)(src + (size_t)r*ld + kc*64 + c4);
        float x0 = v.x*scale, x1 = v.y*scale, x2 = v.z*scale, x3 = v.w*scale;
        unsigned h0 = packh(x0, x1), h1 = packh(x2, x3);
        unsigned l0 = packl(x0, x1, h0), l1 = packl(x2, x3, h1);
        int o = r*PW + (c4 >> 1);
        th[o] = h0; th[o+1] = h1;
        tl[o] = l0; tl[o+1] = l1;
    }
}

// copy a preconverted NW-word tile pair (global -> smem); NTHR threads
template<int NW, int NTHR>
static __device__ __forceinline__ void copy_tileN(const unsigned* __restrict__ gh,
                                                  const unsigned* __restrict__ gl,
                                                  unsigned* th, unsigned* tl, int tid) {
#pragma unroll
    for (int it = 0; it < (NW/4 + NTHR - 1)/NTHR; it++) {
        int idx = it*NTHR + tid;
        if (idx < NW/4) {
            ((uint4*)th)[idx] = ((const uint4*)gh)[idx];
            ((uint4*)tl)[idx] = ((const uint4*)gl)[idx];
        }
    }
}

// warp GEMM over one K=64 chunk via ldmatrix: C[m0..+16][n0..+NT*8] += A @ B^T (bf16x3)
template<int NT>
static __device__ __forceinline__ void wgemm(unsigned AhB, unsigned AlB,
                                             unsigned BhB, unsigned BlB,
                                             int m0, int n0, int lane, float (*acc)[4]) {
    unsigned aoff = ((m0 + ((lane>>3)&1)*8 + (lane&7))*PW + ((lane>>4)<<2))*4;
    unsigned boff = ((n0 + (lane>>4)*8 + (lane&7))*PW + (((lane>>3)&1)<<2))*4;
#pragma unroll
    for (int ks = 0; ks < 4; ks++) {
        unsigned ka = ks*32;
        unsigned ah[4], al[4];
        ldsm4(ah, AhB + aoff + ka);
        ldsm4(al, AlB + aoff + ka);
#pragma unroll
        for (int ntp = 0; ntp < NT/2; ntp++) {
            unsigned bh[4], bl[4];
            unsigned bo = boff + ntp*(16*PW*4) + ka;
            ldsm4(bh, BhB + bo);
            ldsm4(bl, BlB + bo);
            float* c0 = acc[2*ntp];
            float* c1 = acc[2*ntp + 1];
            mmabf(c0, ah, bh[0], bh[1]);
            mmabf(c0, ah, bl[0], bl[1]);
            mmabf(c0, al, bh[0], bh[1]);
            mmabf(c1, ah, bh[2], bh[3]);
            mmabf(c1, ah, bl[2], bl[3]);
            mmabf(c1, al, bh[2], bh[3]);
        }
    }
}

// ----------------- prep: Weff fold, Wq copy, zero pad, beff -----------------
__global__ void prep_kernel(const float* __restrict__ Wq, const float* __restrict__ Wc1,
                            const float* __restrict__ Wc2, const float* __restrict__ bc1) {
    int blk = blockIdx.x, tid = threadIdx.x;
    if (blk < 50) {
        int j = blk / 25, t = blk % 25;
        if (tid < 128) {
            float s = 0.f;
            for (int o = 0; o < 128; o++)
                s += Wc2[j*128 + o] * Wc1[((size_t)(o*128 + tid))*25 + t];
            g_Weff[blk*128 + tid] = s;
        }
    } else {
        for (int i = tid; i < 16384; i += 256) g_Wqz[i] = Wq[i];
        for (int i = tid; i < 14*128; i += 256) g_Wqz[178*128 + i] = 0.f;
        if (tid < 2) {
            float s = 0.f;
            for (int o = 0; o < 128; o++) s += Wc2[tid*128 + o] * bc1[o];
            g_beff[tid] = s;
        }
    }
}

// ----------------- prep2: Wz = Weff @ Wq (rows 128-177), zbias = Weff @ bq -----------------
__global__ void prep2_kernel(const float* __restrict__ Wq, const float* __restrict__ bq) {
    int jt = blockIdx.x, tid = threadIdx.x;
    float s = 0.f;
    for (int c = 0; c < 128; c++) s += g_Weff[jt*128 + c] * Wq[c*128 + tid];
    g_Wqz[(128 + jt)*128 + tid] = s;
    if (tid == 0) {
        float z = 0.f;
        for (int c = 0; c < 128; c++) z += g_Weff[jt*128 + c] * bq[c];
        g_zbias[jt] = z;
    }
}

// ----------------- prepW: convert weights to hi/lo word tiles (512 thr) -----------------
__global__ void prepW_kernel(const float* __restrict__ Wk, const float* __restrict__ Wv,
                             const float* __restrict__ Wo) {
    int blk = blockIdx.x, tid = threadIdx.x;
    if (blk < 2) {
        fill_chunkR<192,512>(g_Wqz, 128, blk, 1.f, g_WthQ[blk], g_WtlQ[blk], tid);
    } else {
        int w = (blk - 2) >> 1, kc = (blk - 2) & 1;
        const float* W = (w == 0) ? Wk : (w == 1) ? Wv : Wo;
        fill_chunkR<128,512>(W, 128, kc, 1.f, g_Wth[w][kc], g_Wtl[w][kc], tid);
    }
}

// ----------------- qproj: [q | z] = x_slice @ [Wq;Wz]^T, N=192, 512 thr -----------------
__global__ void __launch_bounds__(512,1) qproj_kernel(const float* __restrict__ x,
                                                      const float* __restrict__ bq) {
    extern __shared__ unsigned smw[];
    unsigned *Ah = smw, *Al = smw + TILE_W, *Bh = smw + 2*TILE_W, *Bl = smw + 2*TILE_W + TILEQ_W;
    unsigned sb = (unsigned)__cvta_generic_to_shared(smw);
    unsigned AhB = sb, AlB = sb + TILE_W*4, BhB = sb + 2*TILE_W*4, BlB = sb + (2*TILE_W + TILEQ_W)*4;
    int tid = threadIdx.x, wid = tid >> 5, lane = tid & 31;
    int g = lane >> 2, tg = lane & 3;
    int b = blockIdx.x >> 7, h = blockIdx.x & 127;
    const float* src = x + (size_t)b*2097152 + (size_t)h*16384;

    float acc[12][4] = {};
    int m0 = (wid >> 1)*16, n0 = (wid & 1)*96;
    for (int kc = 0; kc < 2; kc++) {
        fill_chunkR<128,512>(src, 128, kc, 1.f, Ah, Al, tid);
        copy_tileN<TILEQ_W,512>(g_WthQ[kc], g_WtlQ[kc], Bh, Bl, tid);
        __syncthreads();
        wgemm<12>(AhB, AlB, BhB, BlB, m0, n0, lane, acc);
        __syncthreads();
    }

    float* stage = (float*)smw;
#pragma unroll
    for (int nt = 0; nt < 12; nt++) {
        int m = m0 + g, n = n0 + nt*8 + 2*tg;
        stage[n*132 + m]         = acc[nt][0];
        stage[(n+1)*132 + m]     = acc[nt][1];
        stage[n*132 + m + 8]     = acc[nt][2];
        stage[(n+1)*132 + m + 8] = acc[nt][3];
    }
    __syncthreads();

    float* qd = g_q + (size_t)b*2097152 + (size_t)h*128;
#pragma unroll
    for (int it = 0; it < 8; it++) {
        int idx = it*512 + tid;
        int c = idx >> 5, m4 = (idx & 31)*4;
        float bias = bq[c];
        float4 v = *(float4*)(stage + c*132 + m4);
        v.x += bias; v.y += bias; v.z += bias; v.w += bias;
        *(float4*)(qd + (size_t)c*16384 + m4) = v;
    }
    float* zd = g_z + (size_t)b*1048576 + (size_t)h*128;
#pragma unroll
    for (int it = 0; it < 4; it++) {
        int idx = it*512 + tid;
        if (idx < 1600) {
            int zr = idx >> 5, m4 = (idx & 31)*4;
            float4 v = *(float4*)(stage + (128 + zr)*132 + m4);
            *(float4*)(zd + (size_t)zr*16384 + m4) = v;
        }
    }
}

// ----------------- offset2: 25-tap shifted sum over z + coords -----------------
__global__ void __launch_bounds__(256) offset2_kernel() {
    int p = blockIdx.x*256 + threadIdx.x;
    int b = p >> 14, rem = p & 16383;
    int h = rem >> 7, w = rem & 127;
    const float* zb = g_z + (size_t)b*1048576;
    float a0 = g_beff[0], a1 = g_beff[1];
#pragma unroll
    for (int kh = 0; kh < 5; kh++) {
        int hh = h + kh - 2;
        if ((unsigned)hh > 127u) continue;
#pragma unroll
        for (int kw = 0; kw < 5; kw++) {
            int ww = w + kw - 2;
            if ((unsigned)ww > 127u) continue;
            int t = kh*5 + kw, sp = hh*128 + ww;
            a0 += zb[(size_t)t*16384 + sp]        + g_zbias[t];
            a1 += zb[(size_t)(25 + t)*16384 + sp] + g_zbias[25 + t];
        }
    }
    float off0 = tanhf(a0)*5.f, off1 = tanhf(a1)*5.f;
    g_coords[2*p]     = ((float)w + off0)*(128.f/127.f) - 0.5f;
    g_coords[2*p + 1] = ((float)h + off1)*(128.f/127.f) - 0.5f;
}

// ----------------- k / vT projection (N=128), 512 thr -----------------
__global__ void __launch_bounds__(512,1) pk_kernel(const float* __restrict__ x, int src_sel,
                                                   int blk_mul, int row_mul,
                                                   int wsel, int dst_sel,
                                                   const float* __restrict__ bias,
                                                   const float* __restrict__ rel) {
    extern __shared__ unsigned smw[];
    unsigned *Ah = smw, *Al = smw + TILE_W, *Bh = smw + 2*TILE_W, *Bl = smw + 3*TILE_W;
    unsigned sb = (unsigned)__cvta_generic_to_shared(smw);
    int tid = threadIdx.x, wid = tid >> 5, lane = tid & 31;
    int g = lane >> 2, tg = lane & 3;
    int b = blockIdx.x >> 7, q2 = blockIdx.x & 127;
    const float* src0 = src_sel ? g_xs : x;
    const float* src = src0 + (size_t)b*2097152 + (size_t)q2*blk_mul;
    float* dst = (dst_sel == 0) ? g_k : g_vT;

    float acc[8][4] = {};
    int m0 = (wid >> 1)*16, n0 = (wid & 1)*64;
    for (int kc = 0; kc < 2; kc++) {
        fill_chunkR<128,512>(src, row_mul, kc, 1.f, Ah, Al, tid);
        copy_tileN<TILE_W,512>(g_Wth[wsel][kc], g_Wtl[wsel][kc], Bh, Bl, tid);
        __syncthreads();
        wgemm<8>(sb, sb + TILE_W*4, sb + 2*TILE_W*4, sb + 3*TILE_W*4, m0, n0, lane, acc);
        __syncthreads();
    }

    float* stage = (float*)smw;
#pragma unroll
    for (int nt = 0; nt < 8; nt++) {
        int m = m0 + g, n = n0 + nt*8 + 2*tg;
        stage[n*132 + m]         = acc[nt][0];
        stage[(n+1)*132 + m]     = acc[nt][1];
        stage[n*132 + m + 8]     = acc[nt][2];
        stage[(n+1)*132 + m + 8] = acc[nt][3];
    }
    __syncthreads();

    float* db = dst + (size_t)b*2097152 + (size_t)q2*128;
#pragma unroll
    for (int it = 0; it < 8; it++) {
        int idx = it*512 + tid;
        int c = idx >> 5, m4 = (idx & 31)*4;
        float bc = bias[c];
        float4 v = *(float4*)(stage + c*132 + m4);
        if (rel) {
            float4 rv = *(const float4*)(rel + c*128 + m4);
            v.x += bc + rv.x; v.y += bc + rv.y; v.z += bc + rv.z; v.w += bc + rv.w;
        } else {
            v.x += bc; v.y += bc; v.z += bc; v.w += bc;
        }
        *(float4*)(db + (size_t)c*16384 + m4) = v;
    }
}

// ----------------- bilinear gather -----------------
__global__ void __launch_bounds__(256) sample_kernel(const float* __restrict__ x) {
    int tid = threadIdx.x;
    int lane = tid & 31, wa = tid >> 5;
    int b = blockIdx.x >> 7, h = blockIdx.x & 127;
    const float* xb = x + (size_t)b*2097152;
    for (int w = wa; w < 128; w += 8) {
        size_t p = ((size_t)(b*128 + h))*128 + w;
        float xg = g_coords[2*p], yg = g_coords[2*p + 1];
        float x0 = floorf(xg), y0 = floorf(yg);
        float4 out = make_float4(0.f, 0.f, 0.f, 0.f);
#pragma unroll
        for (int dy = 0; dy < 2; dy++)
#pragma unroll
            for (int dx = 0; dx < 2; dx++) {
                float xi = x0 + (float)dx, yi = y0 + (float)dy;
                float wt = (1.f - fabsf(xg - xi))*(1.f - fabsf(yg - yi));
                bool valid = (xi >= 0.f) && (xi <= 127.f) && (yi >= 0.f) && (yi <= 127.f);
                float wv = valid ? wt : 0.f;
                int ix = min(max((int)xi, 0), 127);
                int iy = min(max((int)yi, 0), 127);
                float4 src = *(const float4*)(xb + ((size_t)(iy*128 + ix))*128 + lane*4);
                out.x += wv*src.x; out.y += wv*src.y; out.z += wv*src.z; out.w += wv*src.w;
            }
        *(float4*)(g_xs + p*128 + lane*4) = out;
    }
}

// ----------------- attention + fused output projection, 512 thr -----------------
__global__ void __launch_bounds__(512,1) attn_kernel(const float* __restrict__ bo,
                                                     float* __restrict__ out) {
    extern __shared__ unsigned smw[];
    unsigned *Ah = smw, *Al = smw + TILE_W, *Bh = smw + 2*TILE_W, *Bl = smw + 3*TILE_W;
    float* red = (float*)(smw + 4*TILE_W);          // 512 floats: [0:256) max, [256:512) sum
    unsigned sb = (unsigned)__cvta_generic_to_shared(smw);
    unsigned AhB = sb, AlB = sb + TILE_W*4, BhB = sb + 2*TILE_W*4, BlB = sb + 3*TILE_W*4;
    int tid = threadIdx.x, wid = tid >> 5, lane = tid & 31;
    int g = lane >> 2, tg = lane & 3;
    int s = blockIdx.x;
    const float* qs = g_q  + (size_t)s*16384;
    const float* ks = g_k  + (size_t)s*16384;
    const float* vs = g_vT + (size_t)s*16384;
    int m0 = (wid >> 1)*16, wx = wid & 1, n0 = wx*64;

    // ---- S = (q*scale) @ k^T : warp tile 16 x 64 ----
    float sacc[8][4] = {};
    for (int kc = 0; kc < 2; kc++) {
        fill_chunkR<128,512>(qs, 128, kc, ATT_SCALE, Ah, Al, tid);
        fill_chunkR<128,512>(ks, 128, kc, 1.f,       Bh, Bl, tid);
        __syncthreads();
        wgemm<8>(AhB, AlB, BhB, BlB, m0, n0, lane, sacc);
        __syncthreads();
    }

    // ---- softmax: rows m0+g, m0+g+8; quad reduce, then combine wx halves via smem ----
    float mx0 = -1e30f, mx1 = -1e30f;
#pragma unroll
    for (int nt = 0; nt < 8; nt++) {
        mx0 = fmaxf(mx0, fmaxf(sacc[nt][0], sacc[nt][1]));
        mx1 = fmaxf(mx1, fmaxf(sacc[nt][2], sacc[nt][3]));
    }
    mx0 = fmaxf(mx0, __shfl_xor_sync(~0u, mx0, 1)); mx0 = fmaxf(mx0, __shfl_xor_sync(~0u, mx0, 2));
    mx1 = fmaxf(mx1, __shfl_xor_sync(~0u, mx1, 1)); mx1 = fmaxf(mx1, __shfl_xor_sync(~0u, mx1, 2));
    if (tg == 0) { red[wx*128 + m0 + g] = mx0; red[wx*128 + m0 + g + 8] = mx1; }
    __syncthreads();
    mx0 = fmaxf(red[m0 + g],     red[128 + m0 + g]);
    mx1 = fmaxf(red[m0 + g + 8], red[128 + m0 + g + 8]);
    float s0 = 0.f, s1 = 0.f;
#pragma unroll
    for (int nt = 0; nt < 8; nt++) {
        sacc[nt][0] = __expf(sacc[nt][0] - mx0); s0 += sacc[nt][0];
        sacc[nt][1] = __expf(sacc[nt][1] - mx0); s0 += sacc[nt][1];
        sacc[nt][2] = __expf(sacc[nt][2] - mx1); s1 += sacc[nt][2];
        sacc[nt][3] = __expf(sacc[nt][3] - mx1); s1 += sacc[nt][3];
    }
    s0 += __shfl_xor_sync(~0u, s0, 1); s0 += __shfl_xor_sync(~0u, s0, 2);
    s1 += __shfl_xor_sync(~0u, s1, 1); s1 += __shfl_xor_sync(~0u, s1, 2);
    if (tg == 0) { red[256 + wx*128 + m0 + g] = s0; red[256 + wx*128 + m0 + g + 8] = s1; }
    __syncthreads();
    float inv0 = 1.f / (red[256 + m0 + g]     + red[384 + m0 + g]);
    float inv1 = 1.f / (red[256 + m0 + g + 8] + red[384 + m0 + g + 8]);

    // ---- PV = P @ vT^T : warp with wx==kc writes its P chunk; all accumulate ----
    float acc2[8][4] = {};
    for (int kc = 0; kc < 2; kc++) {
        if (wx == kc) {
#pragma unroll
            for (int nt = 0; nt < 8; nt++) {
                int wcol = nt*4 + tg;
                float p0 = sacc[nt][0]*inv0, p1 = sacc[nt][1]*inv0;
                float p2 = sacc[nt][2]*inv1, p3 = sacc[nt][3]*inv1;
                unsigned h0 = packh(p0, p1), h1 = packh(p2, p3);
                int o0 = (m0 + g)*PW + wcol, o1 = (m0 + g + 8)*PW + wcol;
                Ah[o0] = h0; Al[o0] = packl(p0, p1, h0);
                Ah[o1] = h1; Al[o1] = packl(p2, p3, h1);
            }
        }
        fill_chunkR<128,512>(vs, 128, kc, 1.f, Bh, Bl, tid);
        __syncthreads();
        wgemm<8>(AhB, AlB, BhB, BlB, m0, n0, lane, acc2);
        __syncthreads();
    }

    // ---- O = PV @ Wo^T : warp with wx==kc writes its PV chunk ----
    float acc3[8][4] = {};
    for (int kc = 0; kc < 2; kc++) {
        if (wx == kc) {
#pragma unroll
            for (int nt = 0; nt < 8; nt++) {
                int wcol = nt*4 + tg;
                float p0 = acc2[nt][0], p1 = acc2[nt][1];
                float p2 = acc2[nt][2], p3 = acc2[nt][3];
                unsigned h0 = packh(p0, p1), h1 = packh(p2, p3);
                int o0 = (m0 + g)*PW + wcol, o1 = (m0 + g + 8)*PW + wcol;
                Ah[o0] = h0; Al[o0] = packl(p0, p1, h0);
                Ah[o1] = h1; Al[o1] = packl(p2, p3, h1);
            }
        }
        copy_tileN<TILE_W,512>(g_Wth[2][kc], g_Wtl[2][kc], Bh, Bl, tid);
        __syncthreads();
        wgemm<8>(AhB, AlB, BhB, BlB, m0, n0, lane, acc3);
        __syncthreads();
    }

    // ---- epilogue ----
    float* ob = out + (size_t)s*16384;
#pragma unroll
    for (int nt = 0; nt < 8; nt++) {
        int n = n0 + nt*8 + 2*tg, m = m0 + g;
        float b0 = bo[n], b1 = bo[n+1];
        *(float2*)(ob + (size_t)m*128 + n)     = make_float2(acc3[nt][0] + b0, acc3[nt][1] + b1);
        *(float2*)(ob + (size_t)(m+8)*128 + n) = make_float2(acc3[nt][2] + b0, acc3[nt][3] + b1);
    }
}

// ----------------- launch -----------------
extern "C" void kernel_launch(void* const* d_in, const int* in_sizes, int n_in,
                              void* d_out, int out_size) {
    const float* x   = (const float*)d_in[0];
    const float* Wq  = (const float*)d_in[2];
    const float* bq  = (const float*)d_in[3];
    const float* Wk  = (const float*)d_in[4];
    const float* bk  = (const float*)d_in[5];
    const float* Wv  = (const float*)d_in[6];
    const float* bv  = (const float*)d_in[7];
    const float* Wo  = (const float*)d_in[8];
    const float* bo  = (const float*)d_in[9];
    const float* Wc1 = (const float*)d_in[10];
    const float* bc1 = (const float*)d_in[11];
    const float* Wc2 = (const float*)d_in[12];
    const float* rb  = (const float*)d_in[13];
    float* out = (float*)d_out;

    cudaFuncSetAttribute(qproj_kernel, cudaFuncAttributeMaxDynamicSharedMemorySize, SMEM_Q);
    cudaFuncSetAttribute(pk_kernel,    cudaFuncAttributeMaxDynamicSharedMemorySize, SMEM_SZ);
    cudaFuncSetAttribute(attn_kernel,  cudaFuncAttributeMaxDynamicSharedMemorySize, SMEM_ATT);

    prep_kernel   <<<51,  256>>>(Wq, Wc1, Wc2, bc1);
    prep2_kernel  <<<50,  128>>>(Wq, bq);
    prepW_kernel  <<<8,   512>>>(Wk, Wv, Wo);
    qproj_kernel  <<<512, 512, SMEM_Q>>>(x, bq);
    offset2_kernel<<<256, 256>>>();
    sample_kernel <<<512, 256>>>(x);
    pk_kernel     <<<512, 512, SMEM_SZ>>>(x, 1, 16384, 128,   0, 0, bk, nullptr);  // k per (b,h)
    pk_kernel     <<<512, 512, SMEM_SZ>>>(x, 1, 128,   16384, 1, 1, bv, rb);       // vT per (b,w)
    attn_kernel   <<<512, 512, SMEM_ATT>>>(bo, out);
}